// round 6
// baseline (speedup 1.0000x reference)
#include <cuda_runtime.h>

#define T_FULL 529
#define N_NEU  1024
#define N_CH   512
#define T_IN   512
#define N_B    16
#define THETA  25.6f
#define BIASV  12.8f

#define NCHUNK 8           // ts chunks of 64
#define NSEG   8           // channel segments per chunk (64 channels each)
#define SEGCAP 640         // padded ts-bytes per (b,chunk,seg); expected ~390
#define RUNCAP 64          // max runs per (b,chunk,seg)
#define NC     64          // neurons per block
#define NBLK   (N_NEU/NC)  // 16
#define DW     568         // deposit length over u (8*71 >= 512+51+1)
#define SEGL   71          // scan segment length

// run-encoded spike lists (ts bytes; each run starts 4-aligned)
__device__ unsigned char  g_ts[N_B][NCHUNK][NSEG][SEGCAP];
__device__ unsigned short g_runs[N_B][NCHUNK][NSEG][RUNCAP]; // (i<<6)|(cnt-1)
__device__ int            g_rcnt[N_B][NCHUNK][NSEG];

// packed per-(i,n) deposit data; slots = {0, p1, p1+1, p3, p3+1}
__device__ float4 g_p4[N_CH * N_NEU];   // d1,d2,d3,d4
__device__ float2 g_p2[N_CH * N_NEU];   // d0, __int_as_float(p1*256 | (p3*256)<<16) [byte offs]

__device__ float g_cval[N_B][NBLK][T_FULL];
__device__ int   g_cidx[N_B][NBLK][T_FULL];

__device__ __forceinline__ float gfun(int j, float w) {
    float r = (float)j * 0.0625f;                  // j/16
    float l = fmaf((float)j, -0.03125f, 1.5f * w); // 1.5w - j/32
    return fmaxf(0.0f, fminf(r, l));
}
__device__ __forceinline__ float d2g(int j, float w) {
    return gfun(j + 1, w) - 2.0f * gfun(j, w) + gfun(j - 1, w);
}

// ---- Precompute deposits per (i, n) in paired pattern {0,p1,p1+1,p3,p3+1} ----
__global__ void prep_kernel(const float* __restrict__ w, int base) {
    int idx = base + blockIdx.x * blockDim.x + threadIdx.x;
    if (idx >= N_CH * N_NEU) return;
    int n = idx & (N_NEU - 1);
    int i = idx >> 10;
    float wv = w[n * N_CH + i];
    int a = (int)floorf(16.0f * wv);
    int b = (int)floorf(48.0f * wv);
    int p1 = (a >= 1) ? a : 1;
    int p3;
    if (b >= p1 + 2)          p3 = b;
    else if (b + 1 >= p1 + 2) p3 = b + 1;
    else                      p3 = 50;          // dummy pair (amps ~0)
    float d0 = d2g(0, wv);
    float d1 = d2g(p1, wv);
    float d2 = d2g(p1 + 1, wv);
    float d3 = d2g(p3, wv);
    float d4 = -(d0 + d1 + d2 + d3);            // exact-zero-sum guard
    g_p4[idx] = make_float4(d1, d2, d3, d4);
    int pp = (p1 * 256) | ((p3 * 256) << 16);   // BYTE offsets (row = 64 floats)
    g_p2[idx] = make_float2(d0, __int_as_float(pp));
}

// ---- Build run-encoded spike lists; each run's ts bytes start 4-aligned ----
__global__ void __launch_bounds__(256) spikes_kernel(const float* __restrict__ x) {
    int b = blockIdx.y, c = blockIdx.x;
    int wid = threadIdx.x >> 5, lane = threadIdx.x & 31;
    const float* xb = x + (size_t)b * N_CH * T_IN + c * 64;
    int cnt = 0, nr = 0;
    for (int ic = 0; ic < 64; ic++) {
        int i = wid * 64 + ic;
        const float* row = xb + i * T_IN;
        bool f0 = row[lane] != 0.0f;
        bool f1 = row[32 + lane] != 0.0f;
        unsigned m0 = __ballot_sync(0xffffffffu, f0);
        unsigned m1 = __ballot_sync(0xffffffffu, f1);
        int tot = __popc(m0) + __popc(m1);
        if (tot > 0 && cnt + tot <= SEGCAP && nr < RUNCAP) {
            if (f0) g_ts[b][c][wid][cnt + __popc(m0 & ((1u << lane) - 1u))] =
                        (unsigned char)lane;
            if (f1) g_ts[b][c][wid][cnt + __popc(m0) + __popc(m1 & ((1u << lane) - 1u))] =
                        (unsigned char)(32 + lane);
            if (lane == 0) g_runs[b][c][wid][nr] = (unsigned short)((i << 6) | (tot - 1));
            nr++;
            cnt = (cnt + tot + 3) & ~3;         // keep next run 4-aligned
        }
    }
    if (lane == 0) g_rcnt[b][c][wid] = nr;
}

// 5-point RMW, forced grouping: 5 ld.shared back-to-back (one latency
// exposure), 5 adds, 5 st.shared. Addresses: a0, aA=a0+o1, aB=a0+o3 with
// +256 B immediates for the paired slots.
__device__ __forceinline__ void deposit5(unsigned a0, unsigned o1b, unsigned o3b,
                                         float d0, float d1, float d2,
                                         float d3, float d4) {
    unsigned aA = a0 + o1b;
    unsigned aB = a0 + o3b;
    asm volatile(
        "{\n\t"
        ".reg .f32 t0,t1,t2,t3,t4;\n\t"
        "ld.shared.f32 t0, [%0];\n\t"
        "ld.shared.f32 t1, [%1];\n\t"
        "ld.shared.f32 t2, [%1+256];\n\t"
        "ld.shared.f32 t3, [%2];\n\t"
        "ld.shared.f32 t4, [%2+256];\n\t"
        "add.f32 t0, t0, %3;\n\t"
        "add.f32 t1, t1, %4;\n\t"
        "add.f32 t2, t2, %5;\n\t"
        "add.f32 t3, t3, %6;\n\t"
        "add.f32 t4, t4, %7;\n\t"
        "st.shared.f32 [%0], t0;\n\t"
        "st.shared.f32 [%1], t1;\n\t"
        "st.shared.f32 [%1+256], t2;\n\t"
        "st.shared.f32 [%2], t3;\n\t"
        "st.shared.f32 [%2+256], t4;\n\t"
        "}"
        :: "r"(a0), "r"(aA), "r"(aB),
           "f"(d0), "f"(d1), "f"(d2), "f"(d3), "f"(d4)
        : "memory");
}

#define DEPOSIT(dts_) deposit5(DlA + (unsigned)(dts_) * 256u, o1b, o3b, d0, d1, d2, d3, d4)

// ---- Main: scatter deposits, double-scan, per-t argmax candidates ----
// Block = (batch b, neuron-chunk nb of 64). 512 threads = 16 warps: warp pair
// (2c, 2c+1) handles ts-chunk c for neuron halves [0,32) / [32,64).
__global__ void __launch_bounds__(512) pot_kernel() {
    extern __shared__ float D[];                              // [DW][NC] 145.4 KB
    __shared__ __align__(16) unsigned char  s_ts[4][NSEG][SEGCAP];   // 20 KB
    __shared__ __align__(16) unsigned short s_rn[4][NSEG][RUNCAP];   // 4 KB
    __shared__ int   s_rc[4][NSEG];
    __shared__ float sA[NCHUNK * NC];
    __shared__ float sB[NCHUNK * NC];

    const int b = blockIdx.y, nb = blockIdx.x;
    const int tid = threadIdx.x;
    const int wid = tid >> 5;
    const int lane = tid & 31;
    const int chunk = wid >> 1;           // 0..7 = ts chunk
    const int half = wid & 1;             // neuron half
    const int n_glob = nb * NC + half * 32 + lane;

    {
        int4* Dz = (int4*)D;
        for (int u = tid; u < DW * NC / 4; u += 512) Dz[u] = make_int4(0, 0, 0, 0);
    }
    __syncthreads();

    // Phase 1/2: deposits, 2-color over ts-chunk parity (span 116 < 128)
    for (int par = 0; par < 2; par++) {
        #pragma unroll
        for (int j = 0; j < 4; j++) {
            int c = 2 * j + par;
            for (int u = tid; u < NSEG * SEGCAP / 16; u += 512)
                ((int4*)s_ts[j])[u] = ((const int4*)g_ts[b][c])[u];
            if (tid < NSEG * RUNCAP * 2 / 16)
                ((int4*)s_rn[j])[tid] = ((const int4*)g_runs[b][c])[tid];
            if (tid < NSEG) s_rc[j][tid] = g_rcnt[b][c][tid];
        }
        __syncthreads();

        if ((chunk & 1) == par) {
            const int j = chunk >> 1;
            const unsigned DlA =
                (unsigned)__cvta_generic_to_shared(D + chunk * 64 * NC + half * 32 + lane);
            for (int seg = 0; seg < NSEG; seg++) {
                const int nr = s_rc[j][seg];
                const unsigned short* rn = s_rn[j][seg];
                const unsigned char*  tl = s_ts[j][seg];
                int pos = 0;
                int r = 0;
                while (r < nr) {
                    const int nb4 = min(4, nr - r);
                    float4 q4[4]; float2 q2[4]; int qn[4];
                    #pragma unroll
                    for (int k = 0; k < 4; k++) {
                        if (k < nb4) {
                            int rv  = rn[r + k];
                            qn[k]   = (rv & 63) + 1;
                            int idx = ((rv >> 6) << 10) + n_glob;
                            q4[k] = g_p4[idx];
                            q2[k] = g_p2[idx];
                        }
                    }
                    #pragma unroll
                    for (int k = 0; k < 4; k++) {
                        if (k < nb4) {
                            const int pp = __float_as_int(q2[k].y);
                            const unsigned o1b = (unsigned)(pp & 0xffff);
                            const unsigned o3b = (unsigned)(pp >> 16) & 0xffffu;
                            const float d0 = q2[k].x;
                            const float d1 = q4[k].x, d2 = q4[k].y;
                            const float d3 = q4[k].z, d4 = q4[k].w;
                            const int cnt = qn[k];
                            const int nfull = cnt >> 2;
                            for (int wq = 0; wq < nfull; wq++) {
                                unsigned tsw = *(const unsigned*)(tl + pos);
                                pos += 4;
                                DEPOSIT(tsw & 0xffu);
                                DEPOSIT((tsw >> 8) & 0xffu);
                                DEPOSIT((tsw >> 16) & 0xffu);
                                DEPOSIT(tsw >> 24);
                            }
                            const int rem = cnt & 3;
                            if (rem) {
                                unsigned tsw = *(const unsigned*)(tl + pos);
                                pos += 4;
                                DEPOSIT(tsw & 0xffu);
                                if (rem > 1) DEPOSIT((tsw >> 8) & 0xffu);
                                if (rem > 2) DEPOSIT((tsw >> 16) & 0xffu);
                            }
                        }
                    }
                    r += nb4;
                }
            }
        }
        __syncthreads();
    }

    // Double cumulative sum over u per neuron: 8 segments x 64 neurons.
    {
        const int sid = tid >> 6;          // 0..7
        const int l   = tid & 63;          // neuron column
        const int u0 = sid * SEGL;
        const int u1 = u0 + SEGL;
        float a = 0.0f, v = 0.0f;
        for (int u = u0; u < u1; u++) { a += D[u * NC + l]; v += a; }
        sA[sid * NC + l] = a;
        sB[sid * NC + l] = v;
        __syncthreads();
        float s = 0.0f, vin = 0.0f;
        for (int m = 0; m < sid; m++) {
            vin += (float)SEGL * s + sB[m * NC + l];
            s   += sA[m * NC + l];
        }
        for (int u = u0; u < u1; u++) {
            s += D[u * NC + l];
            vin += s;
            D[u * NC + l] = vin;                      // pot at t = u - 14
        }
        __syncthreads();
    }

    // Per-t argmax over this block's 64 neurons (staggered to avoid conflicts)
    for (int t = tid; t < T_FULL; t += 512) {
        const float* row = D + (t + 14) * NC;
        float bv = -1e30f; int bi = 0;
        #pragma unroll
        for (int j = 0; j < NC; j++) {
            int nl = (j + lane) & (NC - 1);
            float v = row[nl];
            if (v > bv || (v == bv && nl < bi)) { bv = v; bi = nl; }
        }
        g_cval[b][nb][t] = bv;
        g_cidx[b][nb][t] = nb * NC + bi;
    }
}

// ---- Reduce candidates + sequential WTA (depression uniform per batch) ----
__global__ void wta_kernel(float* __restrict__ out) {
    __shared__ float sv[T_FULL];
    __shared__ int   si[T_FULL];
    int b = blockIdx.x, tid = threadIdx.x;
    if (tid < T_FULL) {
        float bv = -1e30f; int bi = 0;
        #pragma unroll
        for (int c = 0; c < NBLK; c++) {
            float v = g_cval[b][c][tid];
            int  ix = g_cidx[b][c][tid];
            if (v > bv || (v == bv && ix < bi)) { bv = v; bi = ix; }
        }
        sv[tid] = bv + BIASV;
        si[tid] = bi;
    }
    __syncthreads();
    if (tid == 0) {
        float* ob = out + (size_t)b * N_NEU * T_FULL;
        int skip = 0;
        for (int t = 0; t < T_FULL; t++) {
            if (skip > 0) { skip--; continue; }
            if (sv[t] > THETA) {
                ob[(size_t)si[t] * T_FULL + t] = 1.0f;
                skip = 47;                 // clip(dep+48-1, 0, 47)
            }
        }
    }
}

extern "C" void kernel_launch(void* const* d_in, const int* in_sizes, int n_in,
                              void* d_out, int out_size) {
    const float* x;
    const float* w;
    if (in_sizes[0] == N_B * N_CH * T_IN) { x = (const float*)d_in[0]; w = (const float*)d_in[1]; }
    else                                  { x = (const float*)d_in[1]; w = (const float*)d_in[0]; }
    float* out = (float*)d_out;

    cudaFuncSetAttribute(pot_kernel, cudaFuncAttributeMaxDynamicSharedMemorySize,
                         DW * NC * (int)sizeof(float));

    cudaMemsetAsync(d_out, 0, (size_t)out_size * sizeof(float), 0);
    prep_kernel<<<(N_CH * N_NEU / 2 + 255) / 256, 256>>>(w, 0);
    prep_kernel<<<(N_CH * N_NEU / 2 + 255) / 256, 256>>>(w, N_CH * N_NEU / 2);
    spikes_kernel<<<dim3(NCHUNK, N_B), 256>>>(x);
    pot_kernel<<<dim3(NBLK, N_B), 512, DW * NC * (int)sizeof(float)>>>();
    wta_kernel<<<N_B, 544>>>(out);
}

// round 7
// speedup vs baseline: 1.0322x; 1.0322x over previous
#include <cuda_runtime.h>

#define T_FULL 529
#define N_NEU  1024
#define N_CH   512
#define T_IN   512
#define N_B    16
#define THETA  25.6f
#define BIASV  12.8f

#define NCHUNK 16          // ts chunks of 32
#define CTS    32
#define NSEG   8           // channel segments (64 channels each)
#define SEGCAP 192         // ts bytes per (b,chunk,seg); mean ~102, +9 sigma
#define RUNCAP 64
#define NC     32          // neurons per block
#define NBLK   (N_NEU/NC)  // 32
#define PRIV   84          // private rows per chunk (max used row = 31+49 = 80)
#define NSCAN  36          // logical u rows per warp (16*36 = 576 >= 568)
#define UMAX   544         // pot needed for u in [14, 543]
#define TSBUF  1536        // staging bytes per chunk (= NSEG*SEGCAP bound)

__device__ unsigned char  g_tsv[N_B][NCHUNK][NSEG][SEGCAP];
__device__ unsigned short g_runs[N_B][NCHUNK][NSEG][RUNCAP]; // (ic<<6)|(cnt-1)
__device__ int            g_rcnt[N_B][NCHUNK][NSEG];
__device__ int            g_scnt[N_B][NCHUNK][NSEG];

// per-(i,n) deposits at {0, p1, p1+1, p3, p3+1}, pairwise distinct
__device__ float4 g_p4[N_CH * N_NEU];   // d1,d2,d3,d4
__device__ float2 g_p2[N_CH * N_NEU];   // d0, __int_as_float(p1*128 | (p3*128)<<16)

__device__ float g_cval[N_B][NBLK][T_FULL];
__device__ int   g_cidx[N_B][NBLK][T_FULL];

__device__ __forceinline__ float gfun(int j, float w) {
    float r = (float)j * 0.0625f;
    float l = fmaf((float)j, -0.03125f, 1.5f * w);
    return fmaxf(0.0f, fminf(r, l));
}
__device__ __forceinline__ float d2g(int j, float w) {
    return gfun(j + 1, w) - 2.0f * gfun(j, w) + gfun(j - 1, w);
}

__global__ void prep_kernel(const float* __restrict__ w, int base) {
    int idx = base + blockIdx.x * blockDim.x + threadIdx.x;
    if (idx >= N_CH * N_NEU) return;
    int n = idx & (N_NEU - 1);
    int i = idx >> 10;
    float wv = w[n * N_CH + i];
    int a = (int)floorf(16.0f * wv);
    int b = (int)floorf(48.0f * wv);
    int p1 = (a >= 1) ? a : 1;
    int p3;
    if (b >= p1 + 2)          p3 = b;        // <= 48
    else if (b + 1 >= p1 + 2) p3 = b + 1;    // <= 18 here
    else                      p3 = p1 + 2;   // amplitudes 0 in this regime
    float d0 = d2g(0, wv);
    float d1 = d2g(p1, wv);
    float d2 = d2g(p1 + 1, wv);
    float d3 = d2g(p3, wv);
    float d4 = -(d0 + d1 + d2 + d3);         // exact-zero-sum guard
    g_p4[idx] = make_float4(d1, d2, d3, d4);
    int pp = (p1 * 128) | ((p3 * 128) << 16);  // byte offsets (row = 32 floats)
    g_p2[idx] = make_float2(d0, __int_as_float(pp));
}

// ---- spike lists per (b, chunk of 32 ts, channel seg), run-encoded ----
__global__ void __launch_bounds__(256) spikes_kernel(const float* __restrict__ x) {
    int b = blockIdx.y, c = blockIdx.x;
    int seg = threadIdx.x >> 5, lane = threadIdx.x & 31;
    const float* xb = x + (size_t)b * N_CH * T_IN + c * CTS;
    int cnt = 0, nr = 0;
    for (int ic = 0; ic < 64; ic++) {
        int i = seg * 64 + ic;
        bool sp = xb[i * T_IN + lane] != 0.0f;     // lane = local ts, coalesced
        unsigned m = __ballot_sync(0xffffffffu, sp);
        int tot = __popc(m);
        if (tot > 0 && cnt + tot <= SEGCAP && nr < RUNCAP) {
            if (sp) g_tsv[b][c][seg][cnt + __popc(m & ((1u << lane) - 1u))] =
                        (unsigned char)lane;
            if (lane == 0) g_runs[b][c][seg][nr] = (unsigned short)((ic << 6) | (tot - 1));
            nr++; cnt += tot;
        }
    }
    if (lane == 0) { g_rcnt[b][c][seg] = nr; g_scnt[b][c][seg] = cnt; }
}

// 5-point RMW: 5 grouped ld.shared, 5 adds, 5 st.shared; row stride 128 B
__device__ __forceinline__ void deposit5(unsigned a0, unsigned o1b, unsigned o3b,
                                         float d0, float d1, float d2,
                                         float d3, float d4) {
    unsigned aA = a0 + o1b;
    unsigned aB = a0 + o3b;
    asm volatile(
        "{\n\t"
        ".reg .f32 t0,t1,t2,t3,t4;\n\t"
        "ld.shared.f32 t0, [%0];\n\t"
        "ld.shared.f32 t1, [%1];\n\t"
        "ld.shared.f32 t2, [%1+128];\n\t"
        "ld.shared.f32 t3, [%2];\n\t"
        "ld.shared.f32 t4, [%2+128];\n\t"
        "add.f32 t0, t0, %3;\n\t"
        "add.f32 t1, t1, %4;\n\t"
        "add.f32 t2, t2, %5;\n\t"
        "add.f32 t3, t3, %6;\n\t"
        "add.f32 t4, t4, %7;\n\t"
        "st.shared.f32 [%0], t0;\n\t"
        "st.shared.f32 [%1], t1;\n\t"
        "st.shared.f32 [%1+128], t2;\n\t"
        "st.shared.f32 [%2], t3;\n\t"
        "st.shared.f32 [%2+128], t4;\n\t"
        "}"
        :: "r"(a0), "r"(aA), "r"(aB),
           "f"(d0), "f"(d1), "f"(d2), "f"(d3), "f"(d4)
        : "memory");
}

// Dlog[u] = sum of <=3 private rows contributing to logical row u
__device__ __forceinline__ float dlog(const float* __restrict__ D, int u, int lane) {
    float x = 0.0f;
    int c0 = u >> 5, r0 = u & 31;
    #pragma unroll
    for (int k = 0; k < 3; k++) {
        int cc = c0 - k, rr = r0 + 32 * k;
        if (cc >= 0 && cc < NCHUNK && rr < PRIV)
            x += D[(cc * PRIV + rr) * NC + lane];
    }
    return x;
}
// physical row where pot[u] is stored in-place
__device__ __forceinline__ int prow(int u) {
    return (u < 512) ? ((u >> 5) * PRIV + (u & 31)) : (15 * PRIV + (u - 480));
}

// ---- Main: 16 warps = 16 chunks, all active (private regions, no races) ----
__global__ void __launch_bounds__(512) pot_kernel() {
    extern __shared__ float D[];                        // [NCHUNK][PRIV][NC] 172 KB
    __shared__ __align__(16) unsigned char  s_tsb[NCHUNK][TSBUF];     // 24 KB
    __shared__ __align__(16) unsigned short s_rn[NCHUNK][NSEG][RUNCAP]; // 16 KB
    __shared__ int s_nr[NCHUNK][NSEG];
    __shared__ int s_sc[NCHUNK][NSEG];
    __shared__ int s_off[NCHUNK][NSEG];
    __shared__ float sA[NCHUNK * NC], sB[NCHUNK * NC];

    const int b = blockIdx.y, nb = blockIdx.x;
    const int tid = threadIdx.x;
    const int c = tid >> 5;               // warp = chunk
    const int lane = tid & 31;            // neuron
    const int n_glob = nb * NC + lane;

    float* Dp = D + c * PRIV * NC;

    // zero own private region (no sync needed: own-warp use only)
    {
        int4* z = (int4*)Dp;
        #pragma unroll 4
        for (int u = lane; u < PRIV * NC / 4; u += 32) z[u] = make_int4(0, 0, 0, 0);
    }
    // stage own runs (1 KB) + meta
    {
        const int4* src = (const int4*)g_runs[b][c];
        int4* dst = (int4*)s_rn[c];
        for (int u = lane; u < NSEG * RUNCAP * 2 / 16; u += 32) dst[u] = src[u];
    }
    if (lane < NSEG) {
        s_nr[c][lane] = g_rcnt[b][c][lane];
        s_sc[c][lane] = g_scnt[b][c][lane];
    }
    __syncwarp();
    if (lane == 0) {
        int off = 0;
        for (int s = 0; s < NSEG; s++) {
            s_off[c][s] = off;
            off += ((s_sc[c][s] + 3) >> 2) << 2;      // word-aligned compact
        }
    }
    __syncwarp();
    // stage own ts bytes (compact, word copies)
    for (int s = 0; s < NSEG; s++) {
        int nw = (s_sc[c][s] + 3) >> 2;
        const unsigned* src = (const unsigned*)g_tsv[b][c][s];
        unsigned* dst = (unsigned*)(s_tsb[c] + s_off[c][s]);
        for (int l = lane; l < nw; l += 32) dst[l] = src[l];
    }
    __syncwarp();

    // deposits: all 16 warps concurrently, private regions
    const unsigned DlA = (unsigned)__cvta_generic_to_shared(Dp + lane);
    for (int s = 0; s < NSEG; s++) {
        const int nr = s_nr[c][s];
        const unsigned short* rn = s_rn[c][s];
        const unsigned char*  tl = s_tsb[c] + s_off[c][s];
        int pos = 0;
        int r = 0;
        while (r < nr) {
            const int nb4 = min(4, nr - r);
            float4 q4[4]; float2 q2[4]; int qn[4];
            #pragma unroll
            for (int k = 0; k < 4; k++) {
                if (k < nb4) {
                    int rv  = rn[r + k];
                    qn[k]   = (rv & 63) + 1;
                    int idx = (((s << 6) + (rv >> 6)) << 10) + n_glob;
                    q4[k] = g_p4[idx];
                    q2[k] = g_p2[idx];
                }
            }
            #pragma unroll
            for (int k = 0; k < 4; k++) {
                if (k < nb4) {
                    const int pp = __float_as_int(q2[k].y);
                    const unsigned o1b = (unsigned)(pp & 0xffff);
                    const unsigned o3b = (unsigned)(pp >> 16) & 0xffffu;
                    const float d0 = q2[k].x;
                    const float d1 = q4[k].x, d2 = q4[k].y;
                    const float d3 = q4[k].z, d4 = q4[k].w;
                    const int cnt = qn[k];
                    for (int t = 0; t < cnt; t++) {
                        unsigned dts = tl[pos++];
                        deposit5(DlA + dts * 128u, o1b, o3b, d0, d1, d2, d3, d4);
                    }
                }
            }
            r += nb4;
        }
    }
    __syncthreads();

    // double cumulative scan over logical rows u, 16 warps x NSCAN rows
    {
        const int u0 = c * NSCAN;
        const int u1 = min(u0 + NSCAN, 568);
        float a = 0.0f, v = 0.0f;
        for (int u = u0; u < u1; u++) { float xx = dlog(D, u, lane); a += xx; v += a; }
        sA[c * NC + lane] = a;
        sB[c * NC + lane] = v;
        __syncthreads();
        float sacc = 0.0f, vin = 0.0f;
        for (int m = 0; m < c; m++) {
            vin += (float)NSCAN * sacc + sB[m * NC + lane];
            sacc += sA[m * NC + lane];
        }
        const int ue = min(u1, UMAX);
        for (int u = u0; u < ue; u++) {
            sacc += dlog(D, u, lane);
            vin += sacc;
            D[prow(u) * NC + lane] = vin;     // in-place pot store (owner-exclusive)
        }
    }
    __syncthreads();

    // per-t argmax over 32 neurons, staggered conflict-free gather
    for (int t = tid; t < T_FULL; t += 512) {
        const float* row = D + prow(t + 14) * NC;
        float bv = -1e30f; int bi = 0;
        #pragma unroll
        for (int jj = 0; jj < NC; jj++) {
            int nl = (jj + tid) & (NC - 1);
            float v = row[nl];
            if (v > bv || (v == bv && nl < bi)) { bv = v; bi = nl; }
        }
        g_cval[b][nb][t] = bv;
        g_cidx[b][nb][t] = nb * NC + bi;
    }
}

// ---- Reduce candidates + sequential WTA (depression uniform per batch) ----
__global__ void wta_kernel(float* __restrict__ out) {
    __shared__ float sv[T_FULL];
    __shared__ int   si[T_FULL];
    int b = blockIdx.x, tid = threadIdx.x;
    if (tid < T_FULL) {
        float bv = -1e30f; int bi = 0;
        #pragma unroll 8
        for (int cdx = 0; cdx < NBLK; cdx++) {
            float v = g_cval[b][cdx][tid];
            int  ix = g_cidx[b][cdx][tid];
            if (v > bv || (v == bv && ix < bi)) { bv = v; bi = ix; }
        }
        sv[tid] = bv + BIASV;
        si[tid] = bi;
    }
    __syncthreads();
    if (tid == 0) {
        float* ob = out + (size_t)b * N_NEU * T_FULL;
        int skip = 0;
        for (int t = 0; t < T_FULL; t++) {
            if (skip > 0) { skip--; continue; }
            if (sv[t] > THETA) {
                ob[(size_t)si[t] * T_FULL + t] = 1.0f;
                skip = 47;                 // clip(dep+48-1, 0, 47)
            }
        }
    }
}

extern "C" void kernel_launch(void* const* d_in, const int* in_sizes, int n_in,
                              void* d_out, int out_size) {
    const float* x;
    const float* w;
    if (in_sizes[0] == N_B * N_CH * T_IN) { x = (const float*)d_in[0]; w = (const float*)d_in[1]; }
    else                                  { x = (const float*)d_in[1]; w = (const float*)d_in[0]; }
    float* out = (float*)d_out;

    cudaFuncSetAttribute(pot_kernel, cudaFuncAttributeMaxDynamicSharedMemorySize,
                         NCHUNK * PRIV * NC * (int)sizeof(float));

    cudaMemsetAsync(d_out, 0, (size_t)out_size * sizeof(float), 0);
    prep_kernel<<<(N_CH * N_NEU / 2 + 255) / 256, 256>>>(w, 0);
    prep_kernel<<<(N_CH * N_NEU / 2 + 255) / 256, 256>>>(w, N_CH * N_NEU / 2);
    spikes_kernel<<<dim3(NCHUNK, N_B), 256>>>(x);
    pot_kernel<<<dim3(NBLK, N_B), 512, NCHUNK * PRIV * NC * (int)sizeof(float)>>>();
    wta_kernel<<<N_B, 544>>>(out);
}

// round 8
// speedup vs baseline: 1.1891x; 1.1520x over previous
#include <cuda_runtime.h>

#define T_FULL 529
#define N_NEU  1024
#define N_CH   512
#define T_IN   512
#define N_B    16
#define THETA  25.6f
#define BIASV  12.8f

#define NCHUNK 16          // ts chunks of 32
#define CTS    32
#define NSEG   8           // channel segments (64 channels each)
#define SEGCAP 256         // padded ts bytes per (b,chunk,seg); mean ~180
#define RUNCAP 64
#define NC     32          // neurons per block
#define NBLK   (N_NEU/NC)  // 32
#define PRIV   81          // private rows per chunk (max used row = 31+49 = 80)
#define NSCAN  36          // logical u rows per warp (16*36 = 576 >= 568)
#define UMAX   544         // pot needed for u in [14, 542]
#define TSBUF  (NSEG*SEGCAP + 16)   // staging bytes per chunk (+prefetch slack)

__device__ unsigned char  g_tsv[N_B][NCHUNK][NSEG][SEGCAP];
__device__ unsigned short g_runs[N_B][NCHUNK][NSEG][RUNCAP]; // (ic<<6)|(cnt-1)
__device__ int            g_rcnt[N_B][NCHUNK][NSEG];
__device__ int            g_scnt[N_B][NCHUNK][NSEG];         // padded byte count

// per-(i,n) deposits at {0, p1, p1+1, p3, p3+1}, pairwise distinct
__device__ float4 g_p4[N_CH * N_NEU];   // d1,d2,d3,d4
__device__ float2 g_p2[N_CH * N_NEU];   // d0, __int_as_float(p1*128 | (p3*128)<<16)

__device__ float g_cval[N_B][NBLK][T_FULL];
__device__ int   g_cidx[N_B][NBLK][T_FULL];

__device__ __forceinline__ float gfun(int j, float w) {
    float r = (float)j * 0.0625f;
    float l = fmaf((float)j, -0.03125f, 1.5f * w);
    return fmaxf(0.0f, fminf(r, l));
}
__device__ __forceinline__ float d2g(int j, float w) {
    return gfun(j + 1, w) - 2.0f * gfun(j, w) + gfun(j - 1, w);
}

__global__ void prep_kernel(const float* __restrict__ w, int base) {
    int idx = base + blockIdx.x * blockDim.x + threadIdx.x;
    if (idx >= N_CH * N_NEU) return;
    int n = idx & (N_NEU - 1);
    int i = idx >> 10;
    float wv = w[n * N_CH + i];
    int a = (int)floorf(16.0f * wv);
    int b = (int)floorf(48.0f * wv);
    int p1 = (a >= 1) ? a : 1;
    int p3;
    if (b >= p1 + 2)          p3 = b;        // <= 48
    else if (b + 1 >= p1 + 2) p3 = b + 1;
    else                      p3 = p1 + 2;   // amplitudes 0 in this regime
    float d0 = d2g(0, wv);
    float d1 = d2g(p1, wv);
    float d2 = d2g(p1 + 1, wv);
    float d3 = d2g(p3, wv);
    float d4 = -(d0 + d1 + d2 + d3);         // exact-zero-sum guard
    g_p4[idx] = make_float4(d1, d2, d3, d4);
    int pp = (p1 * 128) | ((p3 * 128) << 16);  // byte offsets (row = 32 floats)
    g_p2[idx] = make_float2(d0, __int_as_float(pp));
}

// ---- spike lists per (b, chunk of 32 ts, channel seg); runs 4-byte aligned ----
__global__ void __launch_bounds__(256) spikes_kernel(const float* __restrict__ x) {
    int b = blockIdx.y, c = blockIdx.x;
    int seg = threadIdx.x >> 5, lane = threadIdx.x & 31;
    const float* xb = x + (size_t)b * N_CH * T_IN + c * CTS;
    int cnt = 0, nr = 0;
    for (int ic = 0; ic < 64; ic++) {
        int i = seg * 64 + ic;
        bool sp = xb[i * T_IN + lane] != 0.0f;     // lane = local ts, coalesced
        unsigned m = __ballot_sync(0xffffffffu, sp);
        int tot = __popc(m);
        if (tot > 0 && cnt + tot <= SEGCAP && nr < RUNCAP) {
            if (sp) g_tsv[b][c][seg][cnt + __popc(m & ((1u << lane) - 1u))] =
                        (unsigned char)lane;
            if (lane == 0) g_runs[b][c][seg][nr] = (unsigned short)((ic << 6) | (tot - 1));
            nr++;
            cnt = (cnt + tot + 3) & ~3;            // word-align next run
        }
    }
    if (lane == 0) { g_rcnt[b][c][seg] = nr; g_scnt[b][c][seg] = cnt; }
}

// 5-point RMW: 5 grouped ld.shared, 5 adds, 5 st.shared; row stride 128 B
__device__ __forceinline__ void deposit5(unsigned a0, unsigned o1b, unsigned o3b,
                                         float d0, float d1, float d2,
                                         float d3, float d4) {
    unsigned aA = a0 + o1b;
    unsigned aB = a0 + o3b;
    asm volatile(
        "{\n\t"
        ".reg .f32 t0,t1,t2,t3,t4;\n\t"
        "ld.shared.f32 t0, [%0];\n\t"
        "ld.shared.f32 t1, [%1];\n\t"
        "ld.shared.f32 t2, [%1+128];\n\t"
        "ld.shared.f32 t3, [%2];\n\t"
        "ld.shared.f32 t4, [%2+128];\n\t"
        "add.f32 t0, t0, %3;\n\t"
        "add.f32 t1, t1, %4;\n\t"
        "add.f32 t2, t2, %5;\n\t"
        "add.f32 t3, t3, %6;\n\t"
        "add.f32 t4, t4, %7;\n\t"
        "st.shared.f32 [%0], t0;\n\t"
        "st.shared.f32 [%1], t1;\n\t"
        "st.shared.f32 [%1+128], t2;\n\t"
        "st.shared.f32 [%2], t3;\n\t"
        "st.shared.f32 [%2+128], t4;\n\t"
        "}"
        :: "r"(a0), "r"(aA), "r"(aB),
           "f"(d0), "f"(d1), "f"(d2), "f"(d3), "f"(d4)
        : "memory");
}

#define DEP(x_) deposit5(DlA + (unsigned)(x_) * 128u, o1b, o3b, dd0, dd1, dd2, dd3, dd4)

// load a batch of 4 runs' tables (vector LDGs issued back-to-back)
#define LOADB(P, rbase)                                                \
    {                                                                  \
        _Pragma("unroll")                                              \
        for (int k = 0; k < 4; k++) {                                  \
            int rr_ = (rbase) + k;                                     \
            if (rr_ < nr) {                                            \
                int rv = rn[rr_];                                      \
                P##n[k] = (rv & 63) + 1;                               \
                int idx = (((s << 6) + (rv >> 6)) << 10) + n_glob;     \
                P##4[k] = g_p4[idx];                                   \
                P##2[k] = g_p2[idx];                                   \
            } else P##n[k] = 0;                                        \
        }                                                              \
    }

// process 4 runs; ts words consumed with next-word prefetch
#define PROCB(P)                                                       \
    {                                                                  \
        _Pragma("unroll")                                              \
        for (int k = 0; k < 4; k++) {                                  \
            const int cnt_ = P##n[k];                                  \
            if (cnt_ > 0) {                                            \
                const int pp = __float_as_int(P##2[k].y);              \
                const unsigned o1b = (unsigned)(pp & 0xffff);          \
                const unsigned o3b = (unsigned)(pp >> 16) & 0xffffu;   \
                const float dd0 = P##2[k].x;                           \
                const float dd1 = P##4[k].x, dd2 = P##4[k].y;          \
                const float dd3 = P##4[k].z, dd4 = P##4[k].w;          \
                const unsigned* twp = tw + wpos;                       \
                const int nfull = cnt_ >> 2, rem = cnt_ & 3;           \
                unsigned w0 = twp[0];                                  \
                for (int q = 0; q < nfull; q++) {                      \
                    unsigned wn = twp[q + 1];   /* prefetch */         \
                    DEP(w0 & 0xffu);                                   \
                    DEP((w0 >> 8) & 0xffu);                            \
                    DEP((w0 >> 16) & 0xffu);                           \
                    DEP(w0 >> 24);                                     \
                    w0 = wn;                                           \
                }                                                      \
                if (rem) {                                             \
                    DEP(w0 & 0xffu);                                   \
                    if (rem > 1) DEP((w0 >> 8) & 0xffu);               \
                    if (rem > 2) DEP((w0 >> 16) & 0xffu);              \
                }                                                      \
                wpos += nfull + (rem ? 1 : 0);                         \
            }                                                          \
        }                                                              \
    }

// Dlog[u] = sum of <=3 private rows contributing to logical row u
__device__ __forceinline__ float dlog(const float* __restrict__ D, int u, int lane) {
    float x = 0.0f;
    int c0 = u >> 5, r0 = u & 31;
    #pragma unroll
    for (int k = 0; k < 3; k++) {
        int cc = c0 - k, rr = r0 + 32 * k;
        if (cc >= 0 && cc < NCHUNK && rr < PRIV)
            x += D[(cc * PRIV + rr) * NC + lane];
    }
    return x;
}
__device__ __forceinline__ int prow(int u) {
    return (u < 512) ? ((u >> 5) * PRIV + (u & 31)) : (15 * PRIV + (u - 480));
}

// ---- Main: 16 warps = 16 chunks, all active (private regions, no races) ----
__global__ void __launch_bounds__(512) pot_kernel() {
    extern __shared__ float D[];                        // [NCHUNK][PRIV][NC] 162 KB
    __shared__ __align__(16) unsigned char  s_tsb[NCHUNK][TSBUF];       // 33 KB
    __shared__ __align__(16) unsigned short s_rn[NCHUNK][NSEG][RUNCAP]; // 16 KB
    __shared__ int s_nr[NCHUNK][NSEG];
    __shared__ int s_sc[NCHUNK][NSEG];
    __shared__ int s_off[NCHUNK][NSEG];
    __shared__ float sA[NCHUNK * NC], sB[NCHUNK * NC];

    const int b = blockIdx.y, nb = blockIdx.x;
    const int tid = threadIdx.x;
    const int c = tid >> 5;               // warp = chunk
    const int lane = tid & 31;            // neuron
    const int n_glob = nb * NC + lane;

    float* Dp = D + c * PRIV * NC;

    // zero own private region (own-warp use only)
    {
        float4* z = (float4*)Dp;
        #pragma unroll 4
        for (int u = lane; u < PRIV * NC / 4; u += 32)
            z[u] = make_float4(0.f, 0.f, 0.f, 0.f);
    }
    // stage own runs + meta
    {
        const int4* src = (const int4*)g_runs[b][c];
        int4* dst = (int4*)s_rn[c];
        for (int u = lane; u < NSEG * RUNCAP * 2 / 16; u += 32) dst[u] = src[u];
    }
    if (lane < NSEG) {
        s_nr[c][lane] = g_rcnt[b][c][lane];
        s_sc[c][lane] = g_scnt[b][c][lane];
    }
    __syncwarp();
    if (lane == 0) {
        int off = 0;
        for (int s = 0; s < NSEG; s++) { s_off[c][s] = off; off += s_sc[c][s]; }
    }
    __syncwarp();
    // stage own ts words (compact)
    for (int s = 0; s < NSEG; s++) {
        int nw = s_sc[c][s] >> 2;
        const unsigned* src = (const unsigned*)g_tsv[b][c][s];
        unsigned* dst = (unsigned*)(s_tsb[c] + s_off[c][s]);
        for (int l = lane; l < nw; l += 32) dst[l] = src[l];
    }
    __syncwarp();

    // deposits: all 16 warps concurrently; run-table ping-pong prefetch
    const unsigned DlA = (unsigned)__cvta_generic_to_shared(Dp + lane);
    for (int s = 0; s < NSEG; s++) {
        const int nr = s_nr[c][s];
        const unsigned short* rn = s_rn[c][s];
        const unsigned* tw = (const unsigned*)(s_tsb[c] + s_off[c][s]);
        int wpos = 0;
        float4 A4[4], B4[4]; float2 A2[4], B2[4]; int An[4], Bn[4];
        int r = 0;
        if (nr > 0) {
            LOADB(A, 0);
            while (true) {
                LOADB(B, r + 4);     // in flight during A processing
                PROCB(A);
                r += 4;
                if (r >= nr) break;
                LOADB(A, r + 4);
                PROCB(B);
                r += 4;
                if (r >= nr) break;
            }
        }
    }
    __syncthreads();

    // double cumulative scan over logical rows u, 16 warps x NSCAN rows
    {
        const int u0 = c * NSCAN;
        const int u1 = min(u0 + NSCAN, 568);
        float a = 0.0f, v = 0.0f;
        for (int u = u0; u < u1; u++) { float xx = dlog(D, u, lane); a += xx; v += a; }
        sA[c * NC + lane] = a;
        sB[c * NC + lane] = v;
        __syncthreads();
        float sacc = 0.0f, vin = 0.0f;
        for (int m = 0; m < c; m++) {
            vin += (float)NSCAN * sacc + sB[m * NC + lane];
            sacc += sA[m * NC + lane];
        }
        const int ue = min(u1, UMAX);
        for (int u = u0; u < ue; u++) {
            sacc += dlog(D, u, lane);
            vin += sacc;
            D[prow(u) * NC + lane] = vin;     // in-place pot store (owner-exclusive)
        }
    }
    __syncthreads();

    // per-t argmax over 32 neurons, staggered conflict-free gather
    for (int t = tid; t < T_FULL; t += 512) {
        const float* row = D + prow(t + 14) * NC;
        float bv = -1e30f; int bi = 0;
        #pragma unroll
        for (int jj = 0; jj < NC; jj++) {
            int nl = (jj + tid) & (NC - 1);
            float v = row[nl];
            if (v > bv || (v == bv && nl < bi)) { bv = v; bi = nl; }
        }
        g_cval[b][nb][t] = bv;
        g_cidx[b][nb][t] = nb * NC + bi;
    }
}

// ---- Reduce candidates + sequential WTA (depression uniform per batch) ----
__global__ void wta_kernel(float* __restrict__ out) {
    __shared__ float sv[T_FULL];
    __shared__ int   si[T_FULL];
    int b = blockIdx.x, tid = threadIdx.x;
    if (tid < T_FULL) {
        float bv = -1e30f; int bi = 0;
        #pragma unroll 8
        for (int cdx = 0; cdx < NBLK; cdx++) {
            float v = g_cval[b][cdx][tid];
            int  ix = g_cidx[b][cdx][tid];
            if (v > bv || (v == bv && ix < bi)) { bv = v; bi = ix; }
        }
        sv[tid] = bv + BIASV;
        si[tid] = bi;
    }
    __syncthreads();
    if (tid == 0) {
        float* ob = out + (size_t)b * N_NEU * T_FULL;
        int skip = 0;
        for (int t = 0; t < T_FULL; t++) {
            if (skip > 0) { skip--; continue; }
            if (sv[t] > THETA) {
                ob[(size_t)si[t] * T_FULL + t] = 1.0f;
                skip = 47;                 // clip(dep+48-1, 0, 47)
            }
        }
    }
}

extern "C" void kernel_launch(void* const* d_in, const int* in_sizes, int n_in,
                              void* d_out, int out_size) {
    const float* x;
    const float* w;
    if (in_sizes[0] == N_B * N_CH * T_IN) { x = (const float*)d_in[0]; w = (const float*)d_in[1]; }
    else                                  { x = (const float*)d_in[1]; w = (const float*)d_in[0]; }
    float* out = (float*)d_out;

    cudaFuncSetAttribute(pot_kernel, cudaFuncAttributeMaxDynamicSharedMemorySize,
                         NCHUNK * PRIV * NC * (int)sizeof(float));

    cudaMemsetAsync(d_out, 0, (size_t)out_size * sizeof(float), 0);
    prep_kernel<<<(N_CH * N_NEU / 2 + 255) / 256, 256>>>(w, 0);
    prep_kernel<<<(N_CH * N_NEU / 2 + 255) / 256, 256>>>(w, N_CH * N_NEU / 2);
    spikes_kernel<<<dim3(NCHUNK, N_B), 256>>>(x);
    pot_kernel<<<dim3(NBLK, N_B), 512, NCHUNK * PRIV * NC * (int)sizeof(float)>>>();
    wta_kernel<<<N_B, 544>>>(out);
}

// round 9
// speedup vs baseline: 1.2416x; 1.0442x over previous
#include <cuda_runtime.h>

#define T_FULL 529
#define N_NEU  1024
#define N_CH   512
#define T_IN   512
#define N_B    16
#define THETA  25.6f
#define BIASV  12.8f

#define NCHUNK 16          // ts chunks of 32
#define CTS    32
#define NSEG   8           // channel segments (64 channels each)
#define SEGCAP 256         // padded ts bytes per (b,chunk,seg)
#define RUNCAP 64          // runs per seg (<= 64 channels)
#define RTOT   512         // flattened runs per (b,chunk) (<= 512 channels)
#define TSBUF  (NSEG*SEGCAP)   // flattened ts bytes per chunk
#define NC     32          // neurons per block
#define NBLK   (N_NEU/NC)  // 32
#define PRIV   81          // private rows per chunk (max used row = 31+49 = 80)
#define NSCAN  36          // logical u rows per warp (16*36 >= 568)
#define UMAX   544

__device__ unsigned char  g_tsv[N_B][NCHUNK][NSEG][SEGCAP];
__device__ unsigned short g_runs[N_B][NCHUNK][NSEG][RUNCAP]; // (ic<<6)|(cnt-1)
__device__ int            g_rcnt[N_B][NCHUNK][NSEG];
__device__ int            g_scnt[N_B][NCHUNK][NSEG];         // padded byte count

// per-(i,n) deposits at {0, p1, p1+1, p3, p3+1}, pairwise distinct
__device__ float4 g_p4[N_CH * N_NEU];   // d1,d2,d3,d4
__device__ float2 g_p2[N_CH * N_NEU];   // d0, __int_as_float(p1*128 | (p3*128)<<16)

__device__ float g_cval[N_B][NBLK][T_FULL];
__device__ int   g_cidx[N_B][NBLK][T_FULL];

__device__ __forceinline__ float gfun(int j, float w) {
    float r = (float)j * 0.0625f;
    float l = fmaf((float)j, -0.03125f, 1.5f * w);
    return fmaxf(0.0f, fminf(r, l));
}
__device__ __forceinline__ float d2g(int j, float w) {
    return gfun(j + 1, w) - 2.0f * gfun(j, w) + gfun(j - 1, w);
}

__global__ void prep_kernel(const float* __restrict__ w, int base) {
    int idx = base + blockIdx.x * blockDim.x + threadIdx.x;
    if (idx >= N_CH * N_NEU) return;
    int n = idx & (N_NEU - 1);
    int i = idx >> 10;
    float wv = w[n * N_CH + i];
    int a = (int)floorf(16.0f * wv);
    int b = (int)floorf(48.0f * wv);
    int p1 = (a >= 1) ? a : 1;
    int p3;
    if (b >= p1 + 2)          p3 = b;
    else if (b + 1 >= p1 + 2) p3 = b + 1;
    else                      p3 = p1 + 2;   // amplitudes 0 in this regime
    float d0 = d2g(0, wv);
    float d1 = d2g(p1, wv);
    float d2 = d2g(p1 + 1, wv);
    float d3 = d2g(p3, wv);
    float d4 = -(d0 + d1 + d2 + d3);         // exact-zero-sum guard
    g_p4[idx] = make_float4(d1, d2, d3, d4);
    int pp = (p1 * 128) | ((p3 * 128) << 16);  // byte offsets (row = 32 floats)
    g_p2[idx] = make_float2(d0, __int_as_float(pp));
}

// ---- spike lists per (b, chunk of 32 ts, channel seg); runs 4-byte aligned ----
__global__ void __launch_bounds__(256) spikes_kernel(const float* __restrict__ x) {
    int b = blockIdx.y, c = blockIdx.x;
    int seg = threadIdx.x >> 5, lane = threadIdx.x & 31;
    const float* xb = x + (size_t)b * N_CH * T_IN + c * CTS;
    int cnt = 0, nr = 0;
    for (int ic = 0; ic < 64; ic++) {
        int i = seg * 64 + ic;
        bool sp = xb[i * T_IN + lane] != 0.0f;     // lane = local ts, coalesced
        unsigned m = __ballot_sync(0xffffffffu, sp);
        int tot = __popc(m);
        if (tot > 0 && cnt + tot <= SEGCAP && nr < RUNCAP) {
            if (sp) g_tsv[b][c][seg][cnt + __popc(m & ((1u << lane) - 1u))] =
                        (unsigned char)lane;
            if (lane == 0) g_runs[b][c][seg][nr] = (unsigned short)((ic << 6) | (tot - 1));
            nr++;
            cnt = (cnt + tot + 3) & ~3;            // word-align next run
        }
    }
    if (lane == 0) { g_rcnt[b][c][seg] = nr; g_scnt[b][c][seg] = cnt; }
}

// 5-point RMW: 5 grouped ld.shared, 5 adds, 5 st.shared; row stride 128 B
__device__ __forceinline__ void deposit5(unsigned a0, unsigned o1b, unsigned o3b,
                                         float d0, float d1, float d2,
                                         float d3, float d4) {
    unsigned aA = a0 + o1b;
    unsigned aB = a0 + o3b;
    asm volatile(
        "{\n\t"
        ".reg .f32 t0,t1,t2,t3,t4;\n\t"
        "ld.shared.f32 t0, [%0];\n\t"
        "ld.shared.f32 t1, [%1];\n\t"
        "ld.shared.f32 t2, [%1+128];\n\t"
        "ld.shared.f32 t3, [%2];\n\t"
        "ld.shared.f32 t4, [%2+128];\n\t"
        "add.f32 t0, t0, %3;\n\t"
        "add.f32 t1, t1, %4;\n\t"
        "add.f32 t2, t2, %5;\n\t"
        "add.f32 t3, t3, %6;\n\t"
        "add.f32 t4, t4, %7;\n\t"
        "st.shared.f32 [%0], t0;\n\t"
        "st.shared.f32 [%1], t1;\n\t"
        "st.shared.f32 [%1+128], t2;\n\t"
        "st.shared.f32 [%2], t3;\n\t"
        "st.shared.f32 [%2+128], t4;\n\t"
        "}"
        :: "r"(a0), "r"(aA), "r"(aB),
           "f"(d0), "f"(d1), "f"(d2), "f"(d3), "f"(d4)
        : "memory");
}

#define DEP(x_) deposit5(DlA + (unsigned)(x_) * 128u, o1b, o3b, dd0, dd1, dd2, dd3, dd4)

// load run rr into a slot (predicated; cnt=0 when out of range)
#define LOADR(Q4, Q2, CNT, rr)                                   \
    if ((rr) < NR) {                                             \
        int rv = rn[rr];                                         \
        CNT = (rv & 63) + 1;                                     \
        int idx = ((rv >> 6) << 10) + n_glob;                    \
        Q4 = g_p4[idx];                                          \
        Q2 = g_p2[idx];                                          \
    } else CNT = 0;

// process one run's spikes (ts words consumed with next-word prefetch)
#define PROCR(Q4, Q2, CNT)                                       \
    if (CNT > 0) {                                               \
        const int pp = __float_as_int(Q2.y);                     \
        const unsigned o1b = (unsigned)(pp & 0xffff);            \
        const unsigned o3b = (unsigned)(pp >> 16) & 0xffffu;     \
        const float dd0 = Q2.x;                                  \
        const float dd1 = Q4.x, dd2 = Q4.y;                      \
        const float dd3 = Q4.z, dd4 = Q4.w;                      \
        const int nfull = CNT >> 2, rem = CNT & 3;               \
        unsigned w0 = tw[wpos];                                  \
        for (int q = 0; q < nfull; q++) {                        \
            unsigned wn = tw[wpos + q + 1];                      \
            DEP(w0 & 0xffu); DEP((w0 >> 8) & 0xffu);             \
            DEP((w0 >> 16) & 0xffu); DEP(w0 >> 24);              \
            w0 = wn;                                             \
        }                                                        \
        if (rem) {                                               \
            DEP(w0 & 0xffu);                                     \
            if (rem > 1) DEP((w0 >> 8) & 0xffu);                 \
            if (rem > 2) DEP((w0 >> 16) & 0xffu);                \
        }                                                        \
        wpos += nfull + (rem ? 1 : 0);                           \
    }

// Dlog[u] = sum of <=3 private rows contributing to logical row u
__device__ __forceinline__ float dlog(const float* __restrict__ D, int u, int lane) {
    float x = 0.0f;
    int c0 = u >> 5, r0 = u & 31;
    #pragma unroll
    for (int k = 0; k < 3; k++) {
        int cc = c0 - k, rr = r0 + 32 * k;
        if (cc >= 0 && cc < NCHUNK && rr < PRIV)
            x += D[(cc * PRIV + rr) * NC + lane];
    }
    return x;
}
__device__ __forceinline__ int prow(int u) {
    return (u < 512) ? ((u >> 5) * PRIV + (u & 31)) : (15 * PRIV + (u - 480));
}

// ---- Main: 16 warps = 16 chunks, all active (private regions, no races) ----
__global__ void __launch_bounds__(512) pot_kernel() {
    extern __shared__ float D[];                        // [NCHUNK][PRIV][NC] 162 KB
    __shared__ __align__(16) unsigned char  s_tsb[NCHUNK][TSBUF];   // 32 KB
    __shared__ __align__(16) unsigned short s_rn[NCHUNK][RTOT];     // 16 KB
    __shared__ int s_snr[NCHUNK][NSEG];
    __shared__ int s_ssc[NCHUNK][NSEG];
    __shared__ int s_NR[NCHUNK];
    __shared__ float sA[NCHUNK * NC], sB[NCHUNK * NC];

    const int b = blockIdx.y, nb = blockIdx.x;
    const int tid = threadIdx.x;
    const int c = tid >> 5;               // warp = chunk
    const int lane = tid & 31;            // neuron
    const int n_glob = nb * NC + lane;

    float* Dp = D + c * PRIV * NC;

    // zero own private region (own-warp use only)
    {
        float4* z = (float4*)Dp;
        #pragma unroll 4
        for (int u = lane; u < PRIV * NC / 4; u += 32)
            z[u] = make_float4(0.f, 0.f, 0.f, 0.f);
    }
    if (lane < NSEG) {
        s_snr[c][lane] = g_rcnt[b][c][lane];
        s_ssc[c][lane] = g_scnt[b][c][lane];
    }
    __syncwarp();
    // flatten 8 segment streams into one run stream (+s<<12 makes channel global)
    {
        int roff = 0, toff = 0;
        for (int s = 0; s < NSEG; s++) {
            const int nr_s = s_snr[c][s];
            const int sc_s = s_ssc[c][s];
            const unsigned add = (unsigned)(s << 12);
            const unsigned short* rsrc = g_runs[b][c][s];
            for (int j = lane; j < nr_s; j += 32)
                s_rn[c][roff + j] = (unsigned short)(rsrc[j] + add);
            const unsigned* tsrc = (const unsigned*)g_tsv[b][c][s];
            unsigned* tdst = (unsigned*)(s_tsb[c] + toff);
            for (int j = lane; j < (sc_s >> 2); j += 32) tdst[j] = tsrc[j];
            roff += nr_s; toff += sc_s;
        }
        if (lane == 0) s_NR[c] = roff;
    }
    __syncwarp();

    // deposits: rolling 3-slot pipeline, load run r+2 while processing run r
    {
        const unsigned DlA = (unsigned)__cvta_generic_to_shared(Dp + lane);
        const int NR = s_NR[c];
        const unsigned short* rn = s_rn[c];
        const unsigned* tw = (const unsigned*)s_tsb[c];
        int wpos = 0;
        float4 q40, q41, q42; float2 q20, q21, q22; int n0, n1, n2;
        LOADR(q40, q20, n0, 0);
        LOADR(q41, q21, n1, 1);
        int r = 0;
        while (r < NR) {
            LOADR(q42, q22, n2, r + 2);
            PROCR(q40, q20, n0);
            if (++r >= NR) break;
            LOADR(q40, q20, n0, r + 2);
            PROCR(q41, q21, n1);
            if (++r >= NR) break;
            LOADR(q41, q21, n1, r + 2);
            PROCR(q42, q22, n2);
            ++r;
        }
    }
    __syncthreads();

    // double cumulative scan over logical rows u, 16 warps x NSCAN rows
    {
        const int u0 = c * NSCAN;
        const int u1 = min(u0 + NSCAN, 568);
        float a = 0.0f, v = 0.0f;
        for (int u = u0; u < u1; u++) { float xx = dlog(D, u, lane); a += xx; v += a; }
        sA[c * NC + lane] = a;
        sB[c * NC + lane] = v;
        __syncthreads();
        float sacc = 0.0f, vin = 0.0f;
        for (int m = 0; m < c; m++) {
            vin += (float)NSCAN * sacc + sB[m * NC + lane];
            sacc += sA[m * NC + lane];
        }
        const int ue = min(u1, UMAX);
        for (int u = u0; u < ue; u++) {
            sacc += dlog(D, u, lane);
            vin += sacc;
            D[prow(u) * NC + lane] = vin;     // in-place pot store (owner-exclusive)
        }
    }
    __syncthreads();

    // per-t argmax over 32 neurons, staggered conflict-free gather
    for (int t = tid; t < T_FULL; t += 512) {
        const float* row = D + prow(t + 14) * NC;
        float bv = -1e30f; int bi = 0;
        #pragma unroll
        for (int jj = 0; jj < NC; jj++) {
            int nl = (jj + tid) & (NC - 1);
            float v = row[nl];
            if (v > bv || (v == bv && nl < bi)) { bv = v; bi = nl; }
        }
        g_cval[b][nb][t] = bv;
        g_cidx[b][nb][t] = nb * NC + bi;
    }
}

// ---- Reduce candidates + sequential WTA (depression uniform per batch) ----
__global__ void wta_kernel(float* __restrict__ out) {
    __shared__ float sv[T_FULL];
    __shared__ int   si[T_FULL];
    int b = blockIdx.x, tid = threadIdx.x;
    if (tid < T_FULL) {
        float bv = -1e30f; int bi = 0;
        #pragma unroll 8
        for (int cdx = 0; cdx < NBLK; cdx++) {
            float v = g_cval[b][cdx][tid];
            int  ix = g_cidx[b][cdx][tid];
            if (v > bv || (v == bv && ix < bi)) { bv = v; bi = ix; }
        }
        sv[tid] = bv + BIASV;
        si[tid] = bi;
    }
    __syncthreads();
    if (tid == 0) {
        float* ob = out + (size_t)b * N_NEU * T_FULL;
        int skip = 0;
        for (int t = 0; t < T_FULL; t++) {
            if (skip > 0) { skip--; continue; }
            if (sv[t] > THETA) {
                ob[(size_t)si[t] * T_FULL + t] = 1.0f;
                skip = 47;                 // clip(dep+48-1, 0, 47)
            }
        }
    }
}

extern "C" void kernel_launch(void* const* d_in, const int* in_sizes, int n_in,
                              void* d_out, int out_size) {
    const float* x;
    const float* w;
    if (in_sizes[0] == N_B * N_CH * T_IN) { x = (const float*)d_in[0]; w = (const float*)d_in[1]; }
    else                                  { x = (const float*)d_in[1]; w = (const float*)d_in[0]; }
    float* out = (float*)d_out;

    cudaFuncSetAttribute(pot_kernel, cudaFuncAttributeMaxDynamicSharedMemorySize,
                         NCHUNK * PRIV * NC * (int)sizeof(float));

    cudaMemsetAsync(d_out, 0, (size_t)out_size * sizeof(float), 0);
    prep_kernel<<<(N_CH * N_NEU / 2 + 255) / 256, 256>>>(w, 0);
    prep_kernel<<<(N_CH * N_NEU / 2 + 255) / 256, 256>>>(w, N_CH * N_NEU / 2);
    spikes_kernel<<<dim3(NCHUNK, N_B), 256>>>(x);
    pot_kernel<<<dim3(NBLK, N_B), 512, NCHUNK * PRIV * NC * (int)sizeof(float)>>>();
    wta_kernel<<<N_B, 544>>>(out);
}